// round 1
// baseline (speedup 1.0000x reference)
#include <cuda_runtime.h>
#include <math.h>

// Problem constants (fixed by the dataset reference)
#define BB   2
#define SS   2048
#define DD   4096
#define HH   32
#define KVH  8
#define HDIM 128
#define GG   4          // HH / KVH
#define PP   1024
#define TT   (PP + SS)  // 3072

// ---------------- scratch (no cudaMalloc allowed) ----------------
__device__ float g_q[(size_t)BB * SS * HH * HDIM];     // 67 MB
__device__ float g_k[(size_t)BB * SS * KVH * HDIM];    // 16.8 MB
__device__ float g_v[(size_t)BB * SS * KVH * HDIM];    // 16.8 MB
__device__ float g_attn[(size_t)BB * SS * DD];         // 67 MB

// =================================================================
// Classic fp32 SGEMM: C[M,N] = A[M,K] @ B[K,N], all row-major.
// 128x128 block tile, BK=16, 256 threads, 8x8 per-thread microtile.
// M, N multiples of 128; K multiple of 16.
// =================================================================
__global__ __launch_bounds__(256) void sgemm128(
    const float* __restrict__ A, const float* __restrict__ Bm,
    float* __restrict__ C, int M, int N, int K)
{
    __shared__ float As[16][128];
    __shared__ float Bs[16][128];

    const int tid = threadIdx.x;
    const int br  = blockIdx.y;
    const int bc  = blockIdx.x;
    const int tr  = (tid >> 4) << 3;   // 0..120
    const int tc  = (tid & 15) << 3;   // 0..120

    float acc[8][8];
#pragma unroll
    for (int i = 0; i < 8; i++)
#pragma unroll
        for (int j = 0; j < 8; j++) acc[i][j] = 0.f;

    const int aRow = tid >> 2;          // 0..63
    const int aCol = (tid & 3) << 2;    // 0,4,8,12
    const int bRow = tid >> 5;          // 0..7
    const int bCol = (tid & 31) << 2;   // 0..124

    const float* Ap = A + (size_t)br * 128 * K;
    const float* Bp = Bm + (size_t)bc * 128;

    for (int kt = 0; kt < K; kt += 16) {
        // load A tile (transposed store into As[k][m])
#pragma unroll
        for (int r = 0; r < 128; r += 64) {
            float4 t4 = *(const float4*)(Ap + (size_t)(aRow + r) * K + kt + aCol);
            As[aCol + 0][aRow + r] = t4.x;
            As[aCol + 1][aRow + r] = t4.y;
            As[aCol + 2][aRow + r] = t4.z;
            As[aCol + 3][aRow + r] = t4.w;
        }
        // load B tile
#pragma unroll
        for (int r = 0; r < 16; r += 8) {
            *(float4*)&Bs[bRow + r][bCol] =
                *(const float4*)(Bp + (size_t)(kt + bRow + r) * N + bCol);
        }
        __syncthreads();

#pragma unroll
        for (int k = 0; k < 16; k++) {
            float ra[8], rb[8];
            *(float4*)&ra[0] = *(float4*)&As[k][tr];
            *(float4*)&ra[4] = *(float4*)&As[k][tr + 4];
            *(float4*)&rb[0] = *(float4*)&Bs[k][tc];
            *(float4*)&rb[4] = *(float4*)&Bs[k][tc + 4];
#pragma unroll
            for (int i = 0; i < 8; i++)
#pragma unroll
                for (int j = 0; j < 8; j++)
                    acc[i][j] = fmaf(ra[i], rb[j], acc[i][j]);
        }
        __syncthreads();
    }

#pragma unroll
    for (int i = 0; i < 8; i++) {
        float* Cp = C + (size_t)(br * 128 + tr + i) * N + bc * 128 + tc;
        *(float4*)Cp       = make_float4(acc[i][0], acc[i][1], acc[i][2], acc[i][3]);
        *(float4*)(Cp + 4) = make_float4(acc[i][4], acc[i][5], acc[i][6], acc[i][7]);
    }
}

// =================================================================
// Flash-style fp32 attention.
// Grid: (S/128, H, B). Block: 128 threads; thread t owns query row
// qtile*128 + t. Q tile + K/V key tiles staged in dynamic smem.
// Causal rule: query s attends to keys j <= P + s.
// =================================================================
#define BQ   128
#define BKEY 32
#define ROWF 132   // 128 + 4 pad floats (keeps float4 alignment, kills conflicts)

__global__ __launch_bounds__(128) void attn_kernel(
    const float* __restrict__ q,   // [B,S,H,HD]
    const float* __restrict__ pk,  // [B,P,KV,HD]
    const float* __restrict__ pv,
    const float* __restrict__ kn,  // [B,S,KV,HD]
    const float* __restrict__ vn,
    float* __restrict__ out)       // [B,S,H*HD]
{
    extern __shared__ float sm[];
    float* Qs = sm;                      // BQ   * ROWF
    float* Ks = Qs + BQ * ROWF;          // BKEY * ROWF
    float* Vs = Ks + BKEY * ROWF;        // BKEY * ROWF

    const int qt  = blockIdx.x;
    const int h   = blockIdx.y;
    const int b   = blockIdx.z;
    const int kvh = h / GG;
    const int tid = threadIdx.x;
    const int sg  = qt * BQ + tid;       // global query index in [0,S)

    // cooperative Q tile load (coalesced float4)
    for (int i = tid; i < BQ * 32; i += BQ) {
        int row = i >> 5, c4 = i & 31;
        float4 v4 = *(const float4*)(q +
            (((size_t)(b * SS + qt * BQ + row) * HH + h) << 7) + (c4 << 2));
        *(float4*)&Qs[row * ROWF + (c4 << 2)] = v4;
    }
    __syncthreads();

    float m = -INFINITY, l = 0.f;
    float4 acc[32];
#pragma unroll
    for (int c = 0; c < 32; c++) acc[c] = make_float4(0.f, 0.f, 0.f, 0.f);

    const float scale  = 0.08838834764831845f;   // 1/sqrt(128)
    const int   jallow = PP + sg;                // inclusive causal bound
    const int   kend   = PP + qt * BQ + BQ;      // max keys needed by block (<=TT)

    float sc[BKEY];   // may go to local mem; negligible vs smem traffic

    for (int kt0 = 0; kt0 < kend; kt0 += BKEY) {
        // stage K/V tile
        for (int i = tid; i < BKEY * 32; i += BQ) {
            int j = i >> 5, c4 = i & 31;
            int t = kt0 + j;
            float4 k4 = make_float4(0.f, 0.f, 0.f, 0.f);
            float4 v4 = k4;
            if (t < TT) {
                size_t off;
                const float *kp, *vp;
                if (t < PP) {
                    off = ((size_t)(b * PP + t) * KVH + kvh) << 7;
                    kp = pk; vp = pv;
                } else {
                    off = ((size_t)(b * SS + (t - PP)) * KVH + kvh) << 7;
                    kp = kn; vp = vn;
                }
                k4 = *(const float4*)(kp + off + (c4 << 2));
                v4 = *(const float4*)(vp + off + (c4 << 2));
            }
            *(float4*)&Ks[j * ROWF + (c4 << 2)] = k4;
            *(float4*)&Vs[j * ROWF + (c4 << 2)] = v4;
        }
        __syncthreads();

        // scores for this tile (thread owns one query row)
        float rowmax = -INFINITY;
        for (int j = 0; j < BKEY; j++) {
            float d0 = 0.f, d1 = 0.f, d2 = 0.f, d3 = 0.f;
#pragma unroll
            for (int c4 = 0; c4 < 32; c4++) {
                float4 q4 = *(float4*)&Qs[tid * ROWF + (c4 << 2)];
                float4 k4 = *(float4*)&Ks[j * ROWF + (c4 << 2)];
                d0 = fmaf(q4.x, k4.x, d0);
                d1 = fmaf(q4.y, k4.y, d1);
                d2 = fmaf(q4.z, k4.z, d2);
                d3 = fmaf(q4.w, k4.w, d3);
            }
            float dot = (d0 + d1) + (d2 + d3);
            int t = kt0 + j;
            float s = (t <= jallow) ? dot * scale : -INFINITY;
            sc[j] = s;
            rowmax = fmaxf(rowmax, s);
        }

        // online softmax rescale
        float mnew = fmaxf(m, rowmax);
        float corr = __expf(m - mnew);
        l *= corr;
#pragma unroll
        for (int c = 0; c < 32; c++) {
            acc[c].x *= corr; acc[c].y *= corr;
            acc[c].z *= corr; acc[c].w *= corr;
        }
        for (int j = 0; j < BKEY; j++) {
            float p = __expf(sc[j] - mnew);
            l += p;
#pragma unroll
            for (int c4 = 0; c4 < 32; c4++) {
                float4 v4 = *(float4*)&Vs[j * ROWF + (c4 << 2)];
                acc[c4].x = fmaf(p, v4.x, acc[c4].x);
                acc[c4].y = fmaf(p, v4.y, acc[c4].y);
                acc[c4].z = fmaf(p, v4.z, acc[c4].z);
                acc[c4].w = fmaf(p, v4.w, acc[c4].w);
            }
        }
        m = mnew;
        __syncthreads();   // protect Ks/Vs before next tile overwrites
    }

    const float inv = 1.f / l;
    float* op = out + (size_t)(b * SS + sg) * DD + h * HDIM;
#pragma unroll
    for (int c4 = 0; c4 < 32; c4++) {
        *(float4*)(op + (c4 << 2)) = make_float4(
            acc[c4].x * inv, acc[c4].y * inv, acc[c4].z * inv, acc[c4].w * inv);
    }
}

// =================================================================
// launcher
// =================================================================
extern "C" void kernel_launch(void* const* d_in, const int* in_sizes, int n_in,
                              void* d_out, int out_size)
{
    const float* x  = (const float*)d_in[0];
    const float* pk = (const float*)d_in[1];
    const float* pv = (const float*)d_in[2];
    const float* Wq = (const float*)d_in[3];
    const float* Wk = (const float*)d_in[4];
    const float* Wv = (const float*)d_in[5];
    const float* Wo = (const float*)d_in[6];
    float* out = (float*)d_out;

    float *qb, *kb, *vb, *ab;
    cudaGetSymbolAddress((void**)&qb, g_q);
    cudaGetSymbolAddress((void**)&kb, g_k);
    cudaGetSymbolAddress((void**)&vb, g_v);
    cudaGetSymbolAddress((void**)&ab, g_attn);

    const int M = BB * SS;   // 4096

    // projections
    sgemm128<<<dim3(DD / 128, M / 128), 256>>>(x, Wq, qb, M, DD, DD);
    sgemm128<<<dim3((KVH * HDIM) / 128, M / 128), 256>>>(x, Wk, kb, M, KVH * HDIM, DD);
    sgemm128<<<dim3((KVH * HDIM) / 128, M / 128), 256>>>(x, Wv, vb, M, KVH * HDIM, DD);

    // attention
    const int smem = (BQ * ROWF + 2 * BKEY * ROWF) * (int)sizeof(float);  // 101376 B
    cudaFuncSetAttribute(attn_kernel, cudaFuncAttributeMaxDynamicSharedMemorySize, smem);
    attn_kernel<<<dim3(SS / BQ, HH, BB), BQ, smem>>>(qb, pk, pv, kb, vb, ab);

    // output projection
    sgemm128<<<dim3(DD / 128, M / 128), 256>>>(ab, Wo, out, M, DD, DD);
}

// round 4
// speedup vs baseline: 1.4385x; 1.4385x over previous
#include <cuda_runtime.h>
#include <cuda_bf16.h>
#include <math.h>

// Problem constants (fixed by the dataset reference)
#define BB   2
#define SS   2048
#define DD   4096
#define HH   32
#define KVH  8
#define HDIM 128
#define GG   4
#define PP   1024
#define TT   (PP + SS)
#define MM   (BB * SS)      // 4096 rows
#define KK   DD             // 4096 reduction dim for all projections
#define NKV  (KVH * HDIM)   // 1024

// ---------------- scratch (no cudaMalloc allowed) ----------------
__device__ float g_q[(size_t)MM * DD];
__device__ float g_k[(size_t)MM * NKV];
__device__ float g_v[(size_t)MM * NKV];
__device__ float g_attn[(size_t)MM * DD];

__device__ __nv_bfloat16 g_xhi[(size_t)MM * KK];
__device__ __nv_bfloat16 g_xlo[(size_t)MM * KK];
__device__ __nv_bfloat16 g_ahi[(size_t)MM * KK];
__device__ __nv_bfloat16 g_alo[(size_t)MM * KK];
__device__ __nv_bfloat16 g_wq_hi[(size_t)KK * DD];
__device__ __nv_bfloat16 g_wq_lo[(size_t)KK * DD];
__device__ __nv_bfloat16 g_wk_hi[(size_t)KK * NKV];
__device__ __nv_bfloat16 g_wk_lo[(size_t)KK * NKV];
__device__ __nv_bfloat16 g_wv_hi[(size_t)KK * NKV];
__device__ __nv_bfloat16 g_wv_lo[(size_t)KK * NKV];
__device__ __nv_bfloat16 g_wo_hi[(size_t)KK * DD];
__device__ __nv_bfloat16 g_wo_lo[(size_t)KK * DD];

// =================================================================
// helpers
// =================================================================
__device__ __forceinline__ void split2(float a, float b, unsigned& h, unsigned& l)
{
    __nv_bfloat16 ha = __float2bfloat16(a);
    __nv_bfloat16 hb = __float2bfloat16(b);
    __nv_bfloat16 la = __float2bfloat16(a - __bfloat162float(ha));
    __nv_bfloat16 lb = __float2bfloat16(b - __bfloat162float(hb));
    h = ((unsigned)__bfloat16_as_ushort(hb) << 16) | (unsigned)__bfloat16_as_ushort(ha);
    l = ((unsigned)__bfloat16_as_ushort(lb) << 16) | (unsigned)__bfloat16_as_ushort(la);
}

__device__ __forceinline__ void cp16(void* s, const void* g)
{
    unsigned sa = (unsigned)__cvta_generic_to_shared(s);
    asm volatile("cp.async.cg.shared.global [%0], [%1], 16;\n" :: "r"(sa), "l"(g));
}
__device__ __forceinline__ void cp8(void* s, const void* g)
{
    unsigned sa = (unsigned)__cvta_generic_to_shared(s);
    asm volatile("cp.async.ca.shared.global [%0], [%1], 8;\n" :: "r"(sa), "l"(g));
}
#define CP_COMMIT() asm volatile("cp.async.commit_group;\n")

__device__ __forceinline__ void mma16816(float* c, const unsigned* a, const unsigned* b)
{
    asm volatile(
        "mma.sync.aligned.m16n8k16.row.col.f32.bf16.bf16.f32 "
        "{%0,%1,%2,%3}, {%4,%5,%6,%7}, {%8,%9}, {%0,%1,%2,%3};\n"
        : "+f"(c[0]), "+f"(c[1]), "+f"(c[2]), "+f"(c[3])
        : "r"(a[0]), "r"(a[1]), "r"(a[2]), "r"(a[3]), "r"(b[0]), "r"(b[1]));
}

// =================================================================
// convA: fp32 [M,K] -> mma-fragment layout bf16 hi/lo.
// Layout: per (mblock16 i, kblock16 j): 32 lanes x 16B.
// Lane (g = l>>2, tg = l&3) holds {a0,a1,a2,a3} pairs:
//   a0=(r0,k0..k0+1) a1=(r0+8,k0..) a2=(r0,k0+8..) a3=(r0+8,k0+8..)
// with r0 = i*16+g, k0 = j*16+tg*2.
// =================================================================
__global__ __launch_bounds__(256) void convA(
    const float* __restrict__ X, __nv_bfloat16* __restrict__ hi,
    __nv_bfloat16* __restrict__ lo, int Mt, int Kt)
{
    int t = blockIdx.x * 8 + (threadIdx.x >> 5);
    int lane = threadIdx.x & 31;
    if (t >= Mt * Kt) return;
    int i = t / Kt, j = t - i * Kt;
    int g = lane >> 2, c0 = (lane & 3) * 2;
    int K = Kt * 16;

    const float* p = X + (size_t)(i * 16 + g) * K + j * 16 + c0;
    float2 v0 = *(const float2*)p;
    float2 v1 = *(const float2*)(p + (size_t)8 * K);
    float2 v2 = *(const float2*)(p + 8);
    float2 v3 = *(const float2*)(p + (size_t)8 * K + 8);

    uint4 H, L;
    split2(v0.x, v0.y, H.x, L.x);
    split2(v1.x, v1.y, H.y, L.y);
    split2(v2.x, v2.y, H.z, L.z);
    split2(v3.x, v3.y, H.w, L.w);

    ((uint4*)hi)[(size_t)t * 32 + lane] = H;
    ((uint4*)lo)[(size_t)t * 32 + lane] = L;
}

// =================================================================
// convB: fp32 W[K,N] -> mma B-fragment layout bf16 hi/lo.
// Per (nblock8 nb, kblock16 kb): 32 lanes x 8B.
// Lane: b-reg0 = {W[k0][n], W[k0+1][n]}, b-reg1 = {W[k0+8][n], W[k0+9][n]}
// with n = nb*8+g, k0 = kb*16+tg*2.
// =================================================================
__global__ __launch_bounds__(256) void convB(
    const float* __restrict__ W, __nv_bfloat16* __restrict__ hi,
    __nv_bfloat16* __restrict__ lo, int Nb, int Kt, int N)
{
    int t = blockIdx.x * 8 + (threadIdx.x >> 5);
    int lane = threadIdx.x & 31;
    if (t >= Nb * Kt) return;
    int nb = t / Kt, kb = t - nb * Kt;
    int g = lane >> 2, tg = lane & 3;
    int n = nb * 8 + g;
    int k = kb * 16 + tg * 2;

    const float* p = W + (size_t)k * N + n;
    float b0 = p[0];
    float b1 = p[(size_t)N];
    float b2 = p[(size_t)8 * N];
    float b3 = p[(size_t)9 * N];

    uint2 H, L;
    split2(b0, b1, H.x, L.x);
    split2(b2, b3, H.y, L.y);

    ((uint2*)hi)[(size_t)t * 32 + lane] = H;
    ((uint2*)lo)[(size_t)t * 32 + lane] = L;
}

// =================================================================
// Split-bf16 tensor-core GEMM: C = Ahi*Bhi + Ahi*Blo + Alo*Bhi (fp32 acc)
// Tile 128x128, BK=32, 256 threads (8 warps, 4x2), warp tile 32x64.
// A/B already in fragment-native gmem layout; staged via cp.async,
// double buffered.
// =================================================================
__global__ __launch_bounds__(256) void mma_gemm(
    const __nv_bfloat16* __restrict__ Ahi, const __nv_bfloat16* __restrict__ Alo,
    const __nv_bfloat16* __restrict__ Bhi, const __nv_bfloat16* __restrict__ Blo,
    float* __restrict__ C, int Kt, int N)
{
    extern __shared__ char smem[];
    uint4* AsH = (uint4*)smem;                 // [2][2][8][32]
    uint4* AsL = AsH + 2 * 2 * 8 * 32;         // +1024
    uint2* BsH = (uint2*)(AsL + 2 * 2 * 8 * 32);   // [2][2][16][32]
    uint2* BsL = BsH + 2 * 2 * 16 * 32;

    const int tid = threadIdx.x;
    const int w = tid >> 5, lane = tid & 31;
    const int wm = w >> 1, wn = w & 1;
    const int br = blockIdx.y, bc = blockIdx.x;
    const int nkt = Kt / 2;   // BK=32 -> 2 kblocks per stage

    float acc[2][8][4];
#pragma unroll
    for (int i = 0; i < 2; i++)
#pragma unroll
        for (int j = 0; j < 8; j++)
#pragma unroll
            for (int c = 0; c < 4; c++) acc[i][j][c] = 0.f;

    // stage loader: kt = BK-step index, st = buffer
    auto load_stage = [&](int kt, int st) {
        // A: warp w -> mblock w
        int mbg = br * 8 + w;
#pragma unroll
        for (int kb = 0; kb < 2; kb++) {
            int kbg = kt * 2 + kb;
            size_t src = ((size_t)mbg * Kt + kbg) * 32 + lane;
            int dst = ((st * 2 + kb) * 8 + w) * 32 + lane;
            cp16(&AsH[dst], &((const uint4*)Ahi)[src]);
            cp16(&AsL[dst], &((const uint4*)Alo)[src]);
        }
        // B: warp w handles chunks c = w, w+8, ..., w+56
#pragma unroll
        for (int cc = 0; cc < 8; cc++) {
            int c = w + cc * 8;
            int hilo = c & 1, nb = (c >> 1) & 15, kb = c >> 5;
            int nbg = bc * 16 + nb;
            int kbg = kt * 2 + kb;
            size_t src = ((size_t)nbg * Kt + kbg) * 32 + lane;
            int dst = ((st * 2 + kb) * 16 + nb) * 32 + lane;
            if (hilo == 0) cp8(&BsH[dst], &((const uint2*)Bhi)[src]);
            else           cp8(&BsL[dst], &((const uint2*)Blo)[src]);
        }
        CP_COMMIT();
    };

    load_stage(0, 0);

    for (int kt = 0; kt < nkt; kt++) {
        if (kt + 1 < nkt) {
            load_stage(kt + 1, (kt + 1) & 1);
            asm volatile("cp.async.wait_group 1;\n");
        } else {
            asm volatile("cp.async.wait_group 0;\n");
        }
        __syncthreads();

        const int st = kt & 1;
#pragma unroll
        for (int kb = 0; kb < 2; kb++) {
            uint4 ah[2], al[2];
#pragma unroll
            for (int mm = 0; mm < 2; mm++) {
                int idx = ((st * 2 + kb) * 8 + wm * 2 + mm) * 32 + lane;
                ah[mm] = AsH[idx];
                al[mm] = AsL[idx];
            }
#pragma unroll
            for (int nb = 0; nb < 8; nb++) {
                int idx = ((st * 2 + kb) * 16 + wn * 8 + nb) * 32 + lane;
                uint2 bh = BsH[idx];
                uint2 bl = BsL[idx];
#pragma unroll
                for (int mm = 0; mm < 2; mm++) {
                    mma16816(acc[mm][nb], (const unsigned*)&ah[mm], (const unsigned*)&bh);
                    mma16816(acc[mm][nb], (const unsigned*)&ah[mm], (const unsigned*)&bl);
                    mma16816(acc[mm][nb], (const unsigned*)&al[mm], (const unsigned*)&bh);
                }
            }
        }
        __syncthreads();
    }

    // writeback
    const int g = lane >> 2, tg = lane & 3;
#pragma unroll
    for (int mm = 0; mm < 2; mm++) {
#pragma unroll
        for (int nb = 0; nb < 8; nb++) {
            int row = br * 128 + (wm * 2 + mm) * 16 + g;
            int col = bc * 128 + (wn * 8 + nb) * 8 + tg * 2;
            *(float2*)(C + (size_t)row * N + col) =
                make_float2(acc[mm][nb][0], acc[mm][nb][1]);
            *(float2*)(C + (size_t)(row + 8) * N + col) =
                make_float2(acc[mm][nb][2], acc[mm][nb][3]);
        }
    }
}

// =================================================================
// Flash-style fp32 attention (unchanged from round 1).
// =================================================================
#define BQ   128
#define BKEY 32
#define ROWF 132

__global__ __launch_bounds__(128) void attn_kernel(
    const float* __restrict__ q,
    const float* __restrict__ pk,
    const float* __restrict__ pv,
    const float* __restrict__ kn,
    const float* __restrict__ vn,
    float* __restrict__ out)
{
    extern __shared__ float sm[];
    float* Qs = sm;
    float* Ks = Qs + BQ * ROWF;
    float* Vs = Ks + BKEY * ROWF;

    const int qt  = blockIdx.x;
    const int h   = blockIdx.y;
    const int b   = blockIdx.z;
    const int kvh = h / GG;
    const int tid = threadIdx.x;
    const int sg  = qt * BQ + tid;

    for (int i = tid; i < BQ * 32; i += BQ) {
        int row = i >> 5, c4 = i & 31;
        float4 v4 = *(const float4*)(q +
            (((size_t)(b * SS + qt * BQ + row) * HH + h) << 7) + (c4 << 2));
        *(float4*)&Qs[row * ROWF + (c4 << 2)] = v4;
    }
    __syncthreads();

    float m = -INFINITY, l = 0.f;
    float4 acc[32];
#pragma unroll
    for (int c = 0; c < 32; c++) acc[c] = make_float4(0.f, 0.f, 0.f, 0.f);

    const float scale  = 0.08838834764831845f;
    const int   jallow = PP + sg;
    const int   kend   = PP + qt * BQ + BQ;

    float sc[BKEY];

    for (int kt0 = 0; kt0 < kend; kt0 += BKEY) {
        for (int i = tid; i < BKEY * 32; i += BQ) {
            int j = i >> 5, c4 = i & 31;
            int t = kt0 + j;
            float4 k4 = make_float4(0.f, 0.f, 0.f, 0.f);
            float4 v4 = k4;
            if (t < TT) {
                size_t off;
                const float *kp, *vp;
                if (t < PP) {
                    off = ((size_t)(b * PP + t) * KVH + kvh) << 7;
                    kp = pk; vp = pv;
                } else {
                    off = ((size_t)(b * SS + (t - PP)) * KVH + kvh) << 7;
                    kp = kn; vp = vn;
                }
                k4 = *(const float4*)(kp + off + (c4 << 2));
                v4 = *(const float4*)(vp + off + (c4 << 2));
            }
            *(float4*)&Ks[j * ROWF + (c4 << 2)] = k4;
            *(float4*)&Vs[j * ROWF + (c4 << 2)] = v4;
        }
        __syncthreads();

        float rowmax = -INFINITY;
        for (int j = 0; j < BKEY; j++) {
            float d0 = 0.f, d1 = 0.f, d2 = 0.f, d3 = 0.f;
#pragma unroll
            for (int c4 = 0; c4 < 32; c4++) {
                float4 q4 = *(float4*)&Qs[tid * ROWF + (c4 << 2)];
                float4 k4 = *(float4*)&Ks[j * ROWF + (c4 << 2)];
                d0 = fmaf(q4.x, k4.x, d0);
                d1 = fmaf(q4.y, k4.y, d1);
                d2 = fmaf(q4.z, k4.z, d2);
                d3 = fmaf(q4.w, k4.w, d3);
            }
            float dot = (d0 + d1) + (d2 + d3);
            int t = kt0 + j;
            float s = (t <= jallow) ? dot * scale : -INFINITY;
            sc[j] = s;
            rowmax = fmaxf(rowmax, s);
        }

        float mnew = fmaxf(m, rowmax);
        float corr = __expf(m - mnew);
        l *= corr;
#pragma unroll
        for (int c = 0; c < 32; c++) {
            acc[c].x *= corr; acc[c].y *= corr;
            acc[c].z *= corr; acc[c].w *= corr;
        }
        for (int j = 0; j < BKEY; j++) {
            float p = __expf(sc[j] - mnew);
            l += p;
#pragma unroll
            for (int c4 = 0; c4 < 32; c4++) {
                float4 v4 = *(float4*)&Vs[j * ROWF + (c4 << 2)];
                acc[c4].x = fmaf(p, v4.x, acc[c4].x);
                acc[c4].y = fmaf(p, v4.y, acc[c4].y);
                acc[c4].z = fmaf(p, v4.z, acc[c4].z);
                acc[c4].w = fmaf(p, v4.w, acc[c4].w);
            }
        }
        m = mnew;
        __syncthreads();
    }

    const float inv = 1.f / l;
    float* op = out + (size_t)(b * SS + sg) * DD + h * HDIM;
#pragma unroll
    for (int c4 = 0; c4 < 32; c4++) {
        *(float4*)(op + (c4 << 2)) = make_float4(
            acc[c4].x * inv, acc[c4].y * inv, acc[c4].z * inv, acc[c4].w * inv);
    }
}

// =================================================================
// launcher
// =================================================================
extern "C" void kernel_launch(void* const* d_in, const int* in_sizes, int n_in,
                              void* d_out, int out_size)
{
    const float* x  = (const float*)d_in[0];
    const float* pk = (const float*)d_in[1];
    const float* pv = (const float*)d_in[2];
    const float* Wq = (const float*)d_in[3];
    const float* Wk = (const float*)d_in[4];
    const float* Wv = (const float*)d_in[5];
    const float* Wo = (const float*)d_in[6];
    float* out = (float*)d_out;

    float *qb, *kb, *vb, *ab;
    cudaGetSymbolAddress((void**)&qb, g_q);
    cudaGetSymbolAddress((void**)&kb, g_k);
    cudaGetSymbolAddress((void**)&vb, g_v);
    cudaGetSymbolAddress((void**)&ab, g_attn);

    __nv_bfloat16 *xhi, *xlo, *ahi, *alo;
    __nv_bfloat16 *wqh, *wql, *wkh, *wkl, *wvh, *wvl, *woh, *wol;
    cudaGetSymbolAddress((void**)&xhi, g_xhi);
    cudaGetSymbolAddress((void**)&xlo, g_xlo);
    cudaGetSymbolAddress((void**)&ahi, g_ahi);
    cudaGetSymbolAddress((void**)&alo, g_alo);
    cudaGetSymbolAddress((void**)&wqh, g_wq_hi);
    cudaGetSymbolAddress((void**)&wql, g_wq_lo);
    cudaGetSymbolAddress((void**)&wkh, g_wk_hi);
    cudaGetSymbolAddress((void**)&wkl, g_wk_lo);
    cudaGetSymbolAddress((void**)&wvh, g_wv_hi);
    cudaGetSymbolAddress((void**)&wvl, g_wv_lo);
    cudaGetSymbolAddress((void**)&woh, g_wo_hi);
    cudaGetSymbolAddress((void**)&wol, g_wo_lo);

    const int Mt = MM / 16;        // 256
    const int Kt = KK / 16;        // 256
    const int NbQ = DD / 8;        // 512
    const int NbKV = NKV / 8;      // 128

    // input conversions (fragment-native pre-swizzle)
    convA<<<(Mt * Kt) / 8, 256>>>(x, xhi, xlo, Mt, Kt);
    convB<<<(NbQ * Kt) / 8, 256>>>(Wq, wqh, wql, NbQ, Kt, DD);
    convB<<<(NbKV * Kt) / 8, 256>>>(Wk, wkh, wkl, NbKV, Kt, NKV);
    convB<<<(NbKV * Kt) / 8, 256>>>(Wv, wvh, wvl, NbKV, Kt, NKV);
    convB<<<(NbQ * Kt) / 8, 256>>>(Wo, woh, wol, NbQ, Kt, DD);

    // projections on the tensor pipe
    const int gemm_smem = 64 * 1024;
    cudaFuncSetAttribute(mma_gemm, cudaFuncAttributeMaxDynamicSharedMemorySize, gemm_smem);
    mma_gemm<<<dim3(DD / 128, MM / 128), 256, gemm_smem>>>(xhi, xlo, wqh, wql, qb, Kt, DD);
    mma_gemm<<<dim3(NKV / 128, MM / 128), 256, gemm_smem>>>(xhi, xlo, wkh, wkl, kb, Kt, NKV);
    mma_gemm<<<dim3(NKV / 128, MM / 128), 256, gemm_smem>>>(xhi, xlo, wvh, wvl, vb, Kt, NKV);

    // attention
    const int smem = (BQ * ROWF + 2 * BKEY * ROWF) * (int)sizeof(float);
    cudaFuncSetAttribute(attn_kernel, cudaFuncAttributeMaxDynamicSharedMemorySize, smem);
    attn_kernel<<<dim3(SS / BQ, HH, BB), BQ, smem>>>(qb, pk, pv, kb, vb, ab);

    // output projection
    convA<<<(Mt * Kt) / 8, 256>>>(ab, ahi, alo, Mt, Kt);
    mma_gemm<<<dim3(DD / 128, MM / 128), 256, gemm_smem>>>(ahi, alo, woh, wol, out, Kt, DD);
}

// round 6
// speedup vs baseline: 3.9058x; 2.7152x over previous
#include <cuda_runtime.h>
#include <cuda_bf16.h>
#include <math.h>

// Problem constants (fixed by the dataset reference)
#define BB   2
#define SS   2048
#define DD   4096
#define HH   32
#define KVH  8
#define HDIM 128
#define GG   4
#define PP   1024
#define TT   (PP + SS)      // 3072
#define MM   (BB * SS)      // 4096
#define KK   DD
#define NKV  (KVH * HDIM)   // 1024

#define KNB  (TT / 8)       // 384 key nblocks (QK B-frags)
#define VKB  (TT / 16)      // 192 key kblocks (PV B-frags)

// ---------------- scratch (no cudaMalloc allowed) ----------------
__device__ float g_q[(size_t)MM * DD];
__device__ float g_k[(size_t)MM * NKV];
__device__ float g_v[(size_t)MM * NKV];

__device__ __nv_bfloat16 g_xhi[(size_t)MM * KK];
__device__ __nv_bfloat16 g_xlo[(size_t)MM * KK];
__device__ __nv_bfloat16 g_ahi[(size_t)MM * KK];   // attention out frags (Wo GEMM A)
__device__ __nv_bfloat16 g_alo[(size_t)MM * KK];
__device__ __nv_bfloat16 g_qhi[(size_t)MM * DD];   // Q frags for attention
__device__ __nv_bfloat16 g_qlo[(size_t)MM * DD];
__device__ __nv_bfloat16 g_wq_hi[(size_t)KK * DD];
__device__ __nv_bfloat16 g_wq_lo[(size_t)KK * DD];
__device__ __nv_bfloat16 g_wk_hi[(size_t)KK * NKV];
__device__ __nv_bfloat16 g_wk_lo[(size_t)KK * NKV];
__device__ __nv_bfloat16 g_wv_hi[(size_t)KK * NKV];
__device__ __nv_bfloat16 g_wv_lo[(size_t)KK * NKV];
__device__ __nv_bfloat16 g_wo_hi[(size_t)KK * DD];
__device__ __nv_bfloat16 g_wo_lo[(size_t)KK * DD];

// K/V fragment caches (merged past+new), hi/lo
__device__ uint2 g_kfh[(size_t)BB * KVH * KNB * 8 * 32];
__device__ uint2 g_kfl[(size_t)BB * KVH * KNB * 8 * 32];
__device__ uint2 g_vfh[(size_t)BB * KVH * 16 * VKB * 32];
__device__ uint2 g_vfl[(size_t)BB * KVH * 16 * VKB * 32];

// =================================================================
// helpers
// =================================================================
__device__ __forceinline__ void split2(float a, float b, unsigned& h, unsigned& l)
{
    __nv_bfloat16 ha = __float2bfloat16(a);
    __nv_bfloat16 hb = __float2bfloat16(b);
    __nv_bfloat16 la = __float2bfloat16(a - __bfloat162float(ha));
    __nv_bfloat16 lb = __float2bfloat16(b - __bfloat162float(hb));
    h = ((unsigned)__bfloat16_as_ushort(hb) << 16) | (unsigned)__bfloat16_as_ushort(ha);
    l = ((unsigned)__bfloat16_as_ushort(lb) << 16) | (unsigned)__bfloat16_as_ushort(la);
}

__device__ __forceinline__ void cp16(void* s, const void* g)
{
    unsigned sa = (unsigned)__cvta_generic_to_shared(s);
    asm volatile("cp.async.cg.shared.global [%0], [%1], 16;\n" :: "r"(sa), "l"(g));
}
__device__ __forceinline__ void cp8(void* s, const void* g)
{
    unsigned sa = (unsigned)__cvta_generic_to_shared(s);
    asm volatile("cp.async.ca.shared.global [%0], [%1], 8;\n" :: "r"(sa), "l"(g));
}
#define CP_COMMIT() asm volatile("cp.async.commit_group;\n")

__device__ __forceinline__ void mma16816(float* c, const unsigned* a, const unsigned* b)
{
    asm volatile(
        "mma.sync.aligned.m16n8k16.row.col.f32.bf16.bf16.f32 "
        "{%0,%1,%2,%3}, {%4,%5,%6,%7}, {%8,%9}, {%0,%1,%2,%3};\n"
        : "+f"(c[0]), "+f"(c[1]), "+f"(c[2]), "+f"(c[3])
        : "r"(a[0]), "r"(a[1]), "r"(a[2]), "r"(a[3]), "r"(b[0]), "r"(b[1]));
}

// =================================================================
// convA: fp32 [M,K] -> mma A-fragment layout bf16 hi/lo.
// =================================================================
__global__ __launch_bounds__(256) void convA(
    const float* __restrict__ X, __nv_bfloat16* __restrict__ hi,
    __nv_bfloat16* __restrict__ lo, int Mt, int Kt)
{
    int t = blockIdx.x * 8 + (threadIdx.x >> 5);
    int lane = threadIdx.x & 31;
    if (t >= Mt * Kt) return;
    int i = t / Kt, j = t - i * Kt;
    int g = lane >> 2, c0 = (lane & 3) * 2;
    int K = Kt * 16;

    const float* p = X + (size_t)(i * 16 + g) * K + j * 16 + c0;
    float2 v0 = *(const float2*)p;
    float2 v1 = *(const float2*)(p + (size_t)8 * K);
    float2 v2 = *(const float2*)(p + 8);
    float2 v3 = *(const float2*)(p + (size_t)8 * K + 8);

    uint4 H, L;
    split2(v0.x, v0.y, H.x, L.x);
    split2(v1.x, v1.y, H.y, L.y);
    split2(v2.x, v2.y, H.z, L.z);
    split2(v3.x, v3.y, H.w, L.w);

    ((uint4*)hi)[(size_t)t * 32 + lane] = H;
    ((uint4*)lo)[(size_t)t * 32 + lane] = L;
}

// =================================================================
// convB: fp32 W[K,N] -> mma B-fragment layout bf16 hi/lo.
// =================================================================
__global__ __launch_bounds__(256) void convB(
    const float* __restrict__ W, __nv_bfloat16* __restrict__ hi,
    __nv_bfloat16* __restrict__ lo, int Nb, int Kt, int N)
{
    int t = blockIdx.x * 8 + (threadIdx.x >> 5);
    int lane = threadIdx.x & 31;
    if (t >= Nb * Kt) return;
    int nb = t / Kt, kb = t - nb * Kt;
    int g = lane >> 2, tg = lane & 3;
    int n = nb * 8 + g;
    int k = kb * 16 + tg * 2;

    const float* p = W + (size_t)k * N + n;
    float b0 = p[0];
    float b1 = p[(size_t)N];
    float b2 = p[(size_t)8 * N];
    float b3 = p[(size_t)9 * N];

    uint2 H, L;
    split2(b0, b1, H.x, L.x);
    split2(b2, b3, H.y, L.y);

    ((uint2*)hi)[(size_t)t * 32 + lane] = H;
    ((uint2*)lo)[(size_t)t * 32 + lane] = L;
}

// =================================================================
// convK: merged KV-cache K -> B-frags for QK^T (n = key t, k = hd).
// Layout: [(b*KVH+kvh)*KNB + nb][kb(8)][lane] uint2.
// =================================================================
__global__ __launch_bounds__(256) void convK(
    const float* __restrict__ pk, const float* __restrict__ knew,
    uint2* __restrict__ hi, uint2* __restrict__ lo)
{
    int t = blockIdx.x * 8 + (threadIdx.x >> 5);
    int lane = threadIdx.x & 31, g = lane >> 2, tg = lane & 3;
    int kb = t & 7;
    int r = t >> 3;
    int nb = r % KNB; r /= KNB;
    int kvh = r & 7, b = r >> 3;

    int tk = nb * 8 + g;
    int k0 = kb * 16 + tg * 2;
    const float* src = (tk < PP)
        ? pk + ((size_t)(b * PP + tk) * KVH + kvh) * HDIM
        : knew + (size_t)(b * SS + tk - PP) * NKV + (size_t)kvh * HDIM;
    float2 v0 = *(const float2*)(src + k0);
    float2 v1 = *(const float2*)(src + k0 + 8);

    uint2 H, L;
    split2(v0.x, v0.y, H.x, L.x);
    split2(v1.x, v1.y, H.y, L.y);
    hi[(size_t)t * 32 + lane] = H;
    lo[(size_t)t * 32 + lane] = L;
}

// =================================================================
// convV: merged KV-cache V -> B-frags for P*V (n = hd, k = key t).
// Layout: [(b*KVH+kvh)*16 + nb][kb(VKB)][lane] uint2.
// (k0..k0+9 stay on one side of the PP boundary since PP%16==0.)
// =================================================================
__global__ __launch_bounds__(256) void convV(
    const float* __restrict__ pv, const float* __restrict__ vnew,
    uint2* __restrict__ hi, uint2* __restrict__ lo)
{
    int t = blockIdx.x * 8 + (threadIdx.x >> 5);
    int lane = threadIdx.x & 31, g = lane >> 2, tg = lane & 3;
    int kb = t % VKB;
    int r = t / VKB;
    int nb = r & 15; r >>= 4;
    int kvh = r & 7, b = r >> 3;

    int n = nb * 8 + g;
    int k0 = kb * 16 + tg * 2;
    const float* base = (k0 < PP)
        ? pv + ((size_t)(b * PP + k0) * KVH + kvh) * HDIM + n
        : vnew + (size_t)(b * SS + k0 - PP) * NKV + (size_t)kvh * HDIM + n;
    // row stride is 1024 floats for both sources
    float v00 = base[0];
    float v01 = base[1024];
    float v08 = base[8 * 1024];
    float v09 = base[9 * 1024];

    uint2 H, L;
    split2(v00, v01, H.x, L.x);
    split2(v08, v09, H.y, L.y);
    hi[(size_t)t * 32 + lane] = H;
    lo[(size_t)t * 32 + lane] = L;
}

// =================================================================
// Split-bf16 tensor-core GEMM (unchanged from round 3/4).
// =================================================================
__global__ __launch_bounds__(256) void mma_gemm(
    const __nv_bfloat16* __restrict__ Ahi, const __nv_bfloat16* __restrict__ Alo,
    const __nv_bfloat16* __restrict__ Bhi, const __nv_bfloat16* __restrict__ Blo,
    float* __restrict__ C, int Kt, int N)
{
    extern __shared__ char smem[];
    uint4* AsH = (uint4*)smem;
    uint4* AsL = AsH + 2 * 2 * 8 * 32;
    uint2* BsH = (uint2*)(AsL + 2 * 2 * 8 * 32);
    uint2* BsL = BsH + 2 * 2 * 16 * 32;

    const int tid = threadIdx.x;
    const int w = tid >> 5, lane = tid & 31;
    const int wm = w >> 1, wn = w & 1;
    const int br = blockIdx.y, bc = blockIdx.x;
    const int nkt = Kt / 2;

    float acc[2][8][4];
#pragma unroll
    for (int i = 0; i < 2; i++)
#pragma unroll
        for (int j = 0; j < 8; j++)
#pragma unroll
            for (int c = 0; c < 4; c++) acc[i][j][c] = 0.f;

    auto load_stage = [&](int kt, int st) {
        int mbg = br * 8 + w;
#pragma unroll
        for (int kb = 0; kb < 2; kb++) {
            int kbg = kt * 2 + kb;
            size_t src = ((size_t)mbg * Kt + kbg) * 32 + lane;
            int dst = ((st * 2 + kb) * 8 + w) * 32 + lane;
            cp16(&AsH[dst], &((const uint4*)Ahi)[src]);
            cp16(&AsL[dst], &((const uint4*)Alo)[src]);
        }
#pragma unroll
        for (int cc = 0; cc < 8; cc++) {
            int c = w + cc * 8;
            int hilo = c & 1, nb = (c >> 1) & 15, kb = c >> 5;
            int nbg = bc * 16 + nb;
            int kbg = kt * 2 + kb;
            size_t src = ((size_t)nbg * Kt + kbg) * 32 + lane;
            int dst = ((st * 2 + kb) * 16 + nb) * 32 + lane;
            if (hilo == 0) cp8(&BsH[dst], &((const uint2*)Bhi)[src]);
            else           cp8(&BsL[dst], &((const uint2*)Blo)[src]);
        }
        CP_COMMIT();
    };

    load_stage(0, 0);

    for (int kt = 0; kt < nkt; kt++) {
        if (kt + 1 < nkt) {
            load_stage(kt + 1, (kt + 1) & 1);
            asm volatile("cp.async.wait_group 1;\n");
        } else {
            asm volatile("cp.async.wait_group 0;\n");
        }
        __syncthreads();

        const int st = kt & 1;
#pragma unroll
        for (int kb = 0; kb < 2; kb++) {
            uint4 ah[2], al[2];
#pragma unroll
            for (int mm = 0; mm < 2; mm++) {
                int idx = ((st * 2 + kb) * 8 + wm * 2 + mm) * 32 + lane;
                ah[mm] = AsH[idx];
                al[mm] = AsL[idx];
            }
#pragma unroll
            for (int nb = 0; nb < 8; nb++) {
                int idx = ((st * 2 + kb) * 16 + wn * 8 + nb) * 32 + lane;
                uint2 bh = BsH[idx];
                uint2 bl = BsL[idx];
#pragma unroll
                for (int mm = 0; mm < 2; mm++) {
                    mma16816(acc[mm][nb], (const unsigned*)&ah[mm], (const unsigned*)&bh);
                    mma16816(acc[mm][nb], (const unsigned*)&ah[mm], (const unsigned*)&bl);
                    mma16816(acc[mm][nb], (const unsigned*)&al[mm], (const unsigned*)&bh);
                }
            }
        }
        __syncthreads();
    }

    const int g = lane >> 2, tg = lane & 3;
#pragma unroll
    for (int mm = 0; mm < 2; mm++) {
#pragma unroll
        for (int nb = 0; nb < 8; nb++) {
            int row = br * 128 + (wm * 2 + mm) * 16 + g;
            int col = bc * 128 + (wn * 8 + nb) * 8 + tg * 2;
            *(float2*)(C + (size_t)row * N + col) =
                make_float2(acc[mm][nb][0], acc[mm][nb][1]);
            *(float2*)(C + (size_t)(row + 8) * N + col) =
                make_float2(acc[mm][nb][2], acc[mm][nb][3]);
        }
    }
}

// =================================================================
// Tensor-core flash attention, split-bf16 (3-pass) QK^T and P*V.
// Grid (S/128, H, B), 256 threads (8 warps). Warp owns 16 query rows.
// No smem: K/V fragments stream from gmem through L1/L2 (shared by
// the 8 warps). Epilogue writes Wo-GEMM A-fragments (hi/lo) directly.
// =================================================================
__global__ __launch_bounds__(256) void attn_mma(
    const uint4* __restrict__ Qh, const uint4* __restrict__ Ql,
    const uint2* __restrict__ Kh, const uint2* __restrict__ Kl,
    const uint2* __restrict__ Vh, const uint2* __restrict__ Vl,
    uint4* __restrict__ Ohi, uint4* __restrict__ Olo)
{
    const int qt = blockIdx.x, h = blockIdx.y, b = blockIdx.z;
    const int kvh = h >> 2;                 // GG = 4
    const int w = threadIdx.x >> 5, lane = threadIdx.x & 31;
    const int g = lane >> 2, tg = lane & 3;

    const int qbase = qt * 128 + w * 16;
    const int mb = (b * SS + qbase) >> 4;
    const size_t qoff = ((size_t)mb * 256 + h * 8) * 32 + lane;

    uint4 qh[8], ql[8];
#pragma unroll
    for (int kb = 0; kb < 8; kb++) {
        qh[kb] = Qh[qoff + (size_t)kb * 32];
        ql[kb] = Ql[qoff + (size_t)kb * 32];
    }

    float O[16][4];
#pragma unroll
    for (int nb = 0; nb < 16; nb++)
#pragma unroll
        for (int c = 0; c < 4; c++) O[nb][c] = 0.f;

    float m0 = -INFINITY, m1 = -INFINITY, l0 = 0.f, l1 = 0.f;
    const int s0 = qbase + g, s1 = s0 + 8;
    const float scale = 0.08838834764831845f;

    const size_t kbase = ((size_t)(b * KVH + kvh) * KNB) * 8 * 32 + lane;
    const size_t vbase = ((size_t)(b * KVH + kvh) * 16) * VKB * 32 + lane;

    const int kend = PP + qbase + 16;
    const int ntiles = (kend + 31) >> 5;

    for (int kt = 0; kt < ntiles; kt++) {
        const int t0 = kt * 32;
        float sc[4][4];
#pragma unroll
        for (int nb = 0; nb < 4; nb++)
#pragma unroll
            for (int c = 0; c < 4; c++) sc[nb][c] = 0.f;

        // ---- scores: S = Q K^T (3-pass split) ----
#pragma unroll
        for (int kb = 0; kb < 8; kb++) {
            uint2 bh[4], bl[4];
#pragma unroll
            for (int nb = 0; nb < 4; nb++) {
                size_t off = kbase + (size_t)((kt * 4 + nb) * 8 + kb) * 32;
                bh[nb] = Kh[off];
                bl[nb] = Kl[off];
            }
#pragma unroll
            for (int nb = 0; nb < 4; nb++) {
                mma16816(sc[nb], (const unsigned*)&qh[kb], (const unsigned*)&bh[nb]);
                mma16816(sc[nb], (const unsigned*)&qh[kb], (const unsigned*)&bl[nb]);
                mma16816(sc[nb], (const unsigned*)&ql[kb], (const unsigned*)&bh[nb]);
            }
        }

        // ---- mask + scale + row maxima ----
        float r0max = -INFINITY, r1max = -INFINITY;
#pragma unroll
        for (int nb = 0; nb < 4; nb++) {
            int tc = t0 + nb * 8 + tg * 2;
            sc[nb][0] = (tc     <= PP + s0) ? sc[nb][0] * scale : -INFINITY;
            sc[nb][1] = (tc + 1 <= PP + s0) ? sc[nb][1] * scale : -INFINITY;
            sc[nb][2] = (tc     <= PP + s1) ? sc[nb][2] * scale : -INFINITY;
            sc[nb][3] = (tc + 1 <= PP + s1) ? sc[nb][3] * scale : -INFINITY;
            r0max = fmaxf(r0max, fmaxf(sc[nb][0], sc[nb][1]));
            r1max = fmaxf(r1max, fmaxf(sc[nb][2], sc[nb][3]));
        }
        r0max = fmaxf(r0max, __shfl_xor_sync(0xffffffffu, r0max, 1));
        r0max = fmaxf(r0max, __shfl_xor_sync(0xffffffffu, r0max, 2));
        r1max = fmaxf(r1max, __shfl_xor_sync(0xffffffffu, r1max, 1));
        r1max = fmaxf(r1max, __shfl_xor_sync(0xffffffffu, r1max, 2));

        float mn0 = fmaxf(m0, r0max), mn1 = fmaxf(m1, r1max);
        float c0 = __expf(m0 - mn0), c1 = __expf(m1 - mn1);
        m0 = mn0; m1 = mn1;
        l0 *= c0; l1 *= c1;
#pragma unroll
        for (int nb = 0; nb < 16; nb++) {
            O[nb][0] *= c0; O[nb][1] *= c0;
            O[nb][2] *= c1; O[nb][3] *= c1;
        }

        // ---- p = exp(s - m) ----
        float p[4][4];
#pragma unroll
        for (int nb = 0; nb < 4; nb++) {
            p[nb][0] = __expf(sc[nb][0] - mn0);
            p[nb][1] = __expf(sc[nb][1] - mn0);
            p[nb][2] = __expf(sc[nb][2] - mn1);
            p[nb][3] = __expf(sc[nb][3] - mn1);
            l0 += p[nb][0] + p[nb][1];
            l1 += p[nb][2] + p[nb][3];
        }

        // ---- O += P V (3-pass split); P frags repacked from score C-frags ----
#pragma unroll
        for (int kb2 = 0; kb2 < 2; kb2++) {
            uint4 ph, pl;
            split2(p[2 * kb2][0],     p[2 * kb2][1],     ph.x, pl.x);
            split2(p[2 * kb2][2],     p[2 * kb2][3],     ph.y, pl.y);
            split2(p[2 * kb2 + 1][0], p[2 * kb2 + 1][1], ph.z, pl.z);
            split2(p[2 * kb2 + 1][2], p[2 * kb2 + 1][3], ph.w, pl.w);
            const int kbg = kt * 2 + kb2;
#pragma unroll
            for (int nb2 = 0; nb2 < 16; nb2++) {
                size_t off = vbase + (size_t)(nb2 * VKB + kbg) * 32;
                uint2 vh2 = Vh[off];
                uint2 vl2 = Vl[off];
                mma16816(O[nb2], (const unsigned*)&ph, (const unsigned*)&vh2);
                mma16816(O[nb2], (const unsigned*)&ph, (const unsigned*)&vl2);
                mma16816(O[nb2], (const unsigned*)&pl, (const unsigned*)&vh2);
            }
        }
    }

    // ---- epilogue: normalize, split hi/lo, write Wo-GEMM A-fragments ----
    l0 += __shfl_xor_sync(0xffffffffu, l0, 1);
    l0 += __shfl_xor_sync(0xffffffffu, l0, 2);
    l1 += __shfl_xor_sync(0xffffffffu, l1, 1);
    l1 += __shfl_xor_sync(0xffffffffu, l1, 2);
    const float inv0 = 1.f / l0, inv1 = 1.f / l1;

#pragma unroll
    for (int j2 = 0; j2 < 8; j2++) {
        uint4 H, L;
        split2(O[2 * j2][0] * inv0,     O[2 * j2][1] * inv0,     H.x, L.x);
        split2(O[2 * j2][2] * inv1,     O[2 * j2][3] * inv1,     H.y, L.y);
        split2(O[2 * j2 + 1][0] * inv0, O[2 * j2 + 1][1] * inv0, H.z, L.z);
        split2(O[2 * j2 + 1][2] * inv1, O[2 * j2 + 1][3] * inv1, H.w, L.w);
        Ohi[qoff + (size_t)j2 * 32] = H;
        Olo[qoff + (size_t)j2 * 32] = L;
    }
}

// =================================================================
// launcher
// =================================================================
extern "C" void kernel_launch(void* const* d_in, const int* in_sizes, int n_in,
                              void* d_out, int out_size)
{
    const float* x  = (const float*)d_in[0];
    const float* pk = (const float*)d_in[1];
    const float* pv = (const float*)d_in[2];
    const float* Wq = (const float*)d_in[3];
    const float* Wk = (const float*)d_in[4];
    const float* Wv = (const float*)d_in[5];
    const float* Wo = (const float*)d_in[6];
    float* out = (float*)d_out;

    float *qb, *kb, *vb;
    cudaGetSymbolAddress((void**)&qb, g_q);
    cudaGetSymbolAddress((void**)&kb, g_k);
    cudaGetSymbolAddress((void**)&vb, g_v);

    __nv_bfloat16 *xhi, *xlo, *ahi, *alo, *qhi, *qlo;
    __nv_bfloat16 *wqh, *wql, *wkh, *wkl, *wvh, *wvl, *woh, *wol;
    cudaGetSymbolAddress((void**)&xhi, g_xhi);
    cudaGetSymbolAddress((void**)&xlo, g_xlo);
    cudaGetSymbolAddress((void**)&ahi, g_ahi);
    cudaGetSymbolAddress((void**)&alo, g_alo);
    cudaGetSymbolAddress((void**)&qhi, g_qhi);
    cudaGetSymbolAddress((void**)&qlo, g_qlo);
    cudaGetSymbolAddress((void**)&wqh, g_wq_hi);
    cudaGetSymbolAddress((void**)&wql, g_wq_lo);
    cudaGetSymbolAddress((void**)&wkh, g_wk_hi);
    cudaGetSymbolAddress((void**)&wkl, g_wk_lo);
    cudaGetSymbolAddress((void**)&wvh, g_wv_hi);
    cudaGetSymbolAddress((void**)&wvl, g_wv_lo);
    cudaGetSymbolAddress((void**)&woh, g_wo_hi);
    cudaGetSymbolAddress((void**)&wol, g_wo_lo);

    uint2 *kfh, *kfl, *vfh, *vfl;
    cudaGetSymbolAddress((void**)&kfh, g_kfh);
    cudaGetSymbolAddress((void**)&kfl, g_kfl);
    cudaGetSymbolAddress((void**)&vfh, g_vfh);
    cudaGetSymbolAddress((void**)&vfl, g_vfl);

    const int Mt = MM / 16;        // 256
    const int Kt = KK / 16;        // 256
    const int NbQ = DD / 8;        // 512
    const int NbKV = NKV / 8;      // 128

    // conversions (fragment-native pre-swizzle)
    convA<<<(Mt * Kt) / 8, 256>>>(x, xhi, xlo, Mt, Kt);
    convB<<<(NbQ * Kt) / 8, 256>>>(Wq, wqh, wql, NbQ, Kt, DD);
    convB<<<(NbKV * Kt) / 8, 256>>>(Wk, wkh, wkl, NbKV, Kt, NKV);
    convB<<<(NbKV * Kt) / 8, 256>>>(Wv, wvh, wvl, NbKV, Kt, NKV);
    convB<<<(NbQ * Kt) / 8, 256>>>(Wo, woh, wol, NbQ, Kt, DD);

    // projections on the tensor pipe
    const int gemm_smem = 64 * 1024;
    cudaFuncSetAttribute(mma_gemm, cudaFuncAttributeMaxDynamicSharedMemorySize, gemm_smem);
    mma_gemm<<<dim3(DD / 128, MM / 128), 256, gemm_smem>>>(xhi, xlo, wqh, wql, qb, Kt, DD);
    mma_gemm<<<dim3(NKV / 128, MM / 128), 256, gemm_smem>>>(xhi, xlo, wkh, wkl, kb, Kt, NKV);
    mma_gemm<<<dim3(NKV / 128, MM / 128), 256, gemm_smem>>>(xhi, xlo, wvh, wvl, vb, Kt, NKV);

    // fragment builds for attention
    convA<<<(Mt * Kt) / 8, 256>>>(qb, qhi, qlo, Mt, Kt);
    convK<<<(BB * KVH * KNB * 8) / 8, 256>>>(pk, kb, kfh, kfl);
    convV<<<(BB * KVH * 16 * VKB) / 8, 256>>>(pv, vb, vfh, vfl);

    // tensor-core attention (writes Wo-GEMM A fragments directly)
    attn_mma<<<dim3(SS / 128, HH, BB), 256>>>(
        (const uint4*)qhi, (const uint4*)qlo, kfh, kfl, vfh, vfl,
        (uint4*)ahi, (uint4*)alo);

    // output projection
    mma_gemm<<<dim3(DD / 128, MM / 128), 256, gemm_smem>>>(ahi, alo, woh, wol, out, Kt, DD);
}